// round 6
// baseline (speedup 1.0000x reference)
#include <cuda_runtime.h>
#include <cstdint>

#define B 8192
#define NNODE 64
#define DOBS 16
#define XROW 18
#define XLEN (B * NNODE * XROW)          // 9437184 floats (x region)
#define EPB 630                          // max edge columns per batch
#define ETOT (B * EPB)                   // 5160960 columns
#define KEY_STRIDE 640

__device__ unsigned short g_keys[(size_t)B * KEY_STRIDE];
__device__ int g_cnt[B];
__device__ int g_off[B];
__device__ int g_total;

// ---------------------------------------------------------------------------
// Kernel 1: fused x-write + per-batch edge keys. 128 thr/block.
// ---------------------------------------------------------------------------
__global__ void __launch_bounds__(128) build_edges_x(const float* __restrict__ obs,
                                                     const float* __restrict__ ego,
                                                     const float* __restrict__ other,
                                                     float* __restrict__ out) {
    int b = blockIdx.x;
    int t = threadIdx.x;              // 0..127
    int lane = t & 31, w = t >> 5;

    __shared__ float sy[64];
    __shared__ unsigned long long skey[64];
    __shared__ int spart[128];
    __shared__ int sord[64];
    __shared__ unsigned sbits[5][2];
    __shared__ int warpsum[4];

    const float4* src4 = (const float4*)(obs + (size_t)b * NNODE * DOBS);
    float* xout = out + (size_t)b * NNODE * XROW;

    float4 fa = src4[t];
    float4 fb = src4[t + 128];

    // write obs part of x directly: float4 i -> out row n=i>>2, cols 4(i&3)..+3
    {
        int n = t >> 2, q = t & 3;
        float2* p = (float2*)(xout + n * XROW + q * 4);
        p[0] = make_float2(fa.x, fa.y);
        p[1] = make_float2(fa.z, fa.w);
        if (q == 0) {   // this float4 holds row n's x,y
            sy[n] = fa.y;
            skey[n] = (((unsigned long long)__float_as_uint(fa.x)) << 6) | (unsigned)n;
        }
    }
    {
        int i = t + 128;
        int n = i >> 2, q = i & 3;
        float2* p = (float2*)(xout + n * XROW + q * 4);
        p[0] = make_float2(fb.x, fb.y);
        p[1] = make_float2(fb.z, fb.w);
        if (q == 0) {
            sy[n] = fb.y;
            skey[n] = (((unsigned long long)__float_as_uint(fb.x)) << 6) | (unsigned)n;
        }
    }
    // init columns 16,17
    if (t < 64) {
        float2 iv = (t == 0) ? make_float2(ego[0], ego[1])
                             : make_float2(other[0], other[1]);
        *(float2*)(xout + t * XROW + DOBS) = iv;
    }
    __syncthreads();

    // --- stable rank by x: 128 threads, 32 u64 compares each ---
    {
        int node = t & 63;
        int jbase = (t >> 6) * 32;
        unsigned long long ki = skey[node];
        int r = 0;
#pragma unroll
        for (int jj = 0; jj < 32; jj++) {
            r += (skey[jbase + jj] < ki);
        }
        spart[t] = r;
    }
    __syncthreads();
    if (t < 64) sord[spart[t] + spart[t + 64]] = t;
    __syncthreads();

    // --- ballot masks over sorted positions ---
    const float T1 = (float)(1.0 / 3.0);
    const float T2 = (float)(2.0 / 3.0);
    if (t < 64) {
        int nd = sord[t];
        float ys = sy[nd];
        bool f0 = (ys <= T1) && (ys > 0.0f);
        bool f1 = (ys > T1) && (ys <= T2);
        bool f2 = (ys >= T2) && (ys < 1.0f);
        bool mm[5] = { f0, f1, f2, f0 || f1, f1 || f2 };
#pragma unroll
        for (int m = 0; m < 5; m++) {
            unsigned bal = __ballot_sync(0xffffffffu, mm[m]);
            if (lane == 0) sbits[m][w] = bal;
        }
    }
    __syncthreads();

    // --- per-node neighbor mask (thread t owns node t) ---
    unsigned long long nbr = 0ULL;
    if (t < 64) {
        int r = spart[t] + spart[t + 64];    // sorted position of node t
        float ys = sy[t];
        bool f0 = (ys <= T1) && (ys > 0.0f);
        bool f1 = (ys > T1) && (ys <= T2);
        bool f2 = (ys >= T2) && (ys < 1.0f);
        bool mm[5] = { f0, f1, f2, f0 || f1, f1 || f2 };
#pragma unroll
        for (int m = 0; m < 5; m++) {
            if (mm[m]) {
                unsigned long long bits =
                    ((unsigned long long)sbits[m][1] << 32) | (unsigned long long)sbits[m][0];
                unsigned long long below = bits & ((1ULL << r) - 1ULL);
                unsigned long long above = (r < 63) ? (bits >> (r + 1)) : 0ULL;
                if (below) {
                    int pp = 63 - __clzll(below);
                    nbr |= 1ULL << sord[pp];
                }
                if (above) {
                    int np = r + 1 + (__ffsll((long long)above) - 1);
                    nbr |= 1ULL << sord[np];
                }
            }
        }
    }

    // --- count + block scan (only warps 0,1 carry nonzero) ---
    int c = __popcll(nbr);
    int inc = c;
#pragma unroll
    for (int d = 1; d < 32; d <<= 1) {
        int nv = __shfl_up_sync(0xffffffffu, inc, d);
        if (lane >= d) inc += nv;
    }
    if (lane == 31) warpsum[w] = inc;
    __syncthreads();
    int wpre = (w == 1) ? warpsum[0] : 0;
    int excl = inc - c + wpre;
    if (t == 0) g_cnt[b] = warpsum[0] + warpsum[1];

    // --- write keys: globally sorted by (src=t, dst=bit) ---
    if (t < 64 && nbr) {
        unsigned short* kb = g_keys + (size_t)b * KEY_STRIDE;
        int pos = excl;
        int kbase = t << 6;
        unsigned long long bits = nbr;
        while (bits) {
            int v = __ffsll((long long)bits) - 1;
            bits &= (bits - 1ULL);
            kb[pos++] = (unsigned short)(kbase | v);
        }
    }
}

// ---------------------------------------------------------------------------
// Kernel 2: exclusive scan of g_cnt[8192] -> g_off, + g_total
// ---------------------------------------------------------------------------
__global__ void __launch_bounds__(1024) scan_counts() {
    int t = threadIdx.x;
    int lane = t & 31, wid = t >> 5;
    __shared__ int wsum[32];

    int base = t * 8;
    int v[8];
    int s = 0;
#pragma unroll
    for (int i = 0; i < 8; i++) {
        v[i] = s;
        s += g_cnt[base + i];
    }
    int inc = s;
#pragma unroll
    for (int d = 1; d < 32; d <<= 1) {
        int nv = __shfl_up_sync(0xffffffffu, inc, d);
        if (lane >= d) inc += nv;
    }
    if (lane == 31) wsum[wid] = inc;
    __syncthreads();
    if (wid == 0) {
        int wv = wsum[lane];
        int winc = wv;
#pragma unroll
        for (int d = 1; d < 32; d <<= 1) {
            int nv = __shfl_up_sync(0xffffffffu, winc, d);
            if (lane >= d) winc += nv;
        }
        wsum[lane] = winc - wv;   // exclusive warp offsets
    }
    __syncthreads();
    int excl = inc - s + wsum[wid];
#pragma unroll
    for (int i = 0; i < 8; i++) g_off[base + i] = excl + v[i];
    if (t == 1023) g_total = excl + s;
}

// ---------------------------------------------------------------------------
// Kernel 3: scatter valid edges + this block's share of the -1 pad
// ---------------------------------------------------------------------------
__global__ void __launch_bounds__(256) scatter_pad(float* __restrict__ out) {
    int b = blockIdx.x;
    int t = threadIdx.x;
    int cnt = g_cnt[b];
    int off = g_off[b];
    const unsigned short* kb = g_keys + (size_t)b * KEY_STRIDE;
    float* src_out = out + XLEN;
    float* dst_out = out + XLEN + ETOT;
    int nb = b * NNODE;
    for (int i = t; i < cnt; i += 256) {
        int k = kb[i];
        src_out[off + i] = (float)(nb + (k >> 6));
        dst_out[off + i] = (float)(nb + (k & 63));
    }
    // pad share
    int T = g_total;
    int P = ETOT - T;
    int chunk = (P + B - 1) / B;
    int start = T + b * chunk;
    int end = start + chunk;
    if (end > ETOT) end = ETOT;
    for (int i = start + t; i < end; i += 256) {
        src_out[i] = -1.0f;
        dst_out[i] = -1.0f;
    }
}

// ---------------------------------------------------------------------------
extern "C" void kernel_launch(void* const* d_in, const int* in_sizes, int n_in,
                              void* d_out, int out_size) {
    const float* obs = (const float*)d_in[0];
    const float* ego = (const float*)d_in[1];
    const float* other = (const float*)d_in[2];
    float* out = (float*)d_out;

    build_edges_x<<<B, 128>>>(obs, ego, other, out);
    scan_counts<<<1, 1024>>>();
    scatter_pad<<<B, 256>>>(out);
}